// round 9
// baseline (speedup 1.0000x reference)
#include <cuda_runtime.h>
#include <cstdint>

#define NEURONS  4096
#define KSEL     512
#define NTHREADS 256
#define VPT      4                 // float4 loads per thread (16 elems/thread)
#define NWARPS   (NTHREADS / 32)
#define FC_CAP   256
#define SENT     0xFFFFFFFFu

// Integer-domain histogram window (bit-monotone for positive floats):
// bins of width 2^13 ulps starting at 0x3F866000 (~1.0498), 256 bins -> hi ~1.2998.
// Threshold for K/N=0.125 on N(0,1) rows is 1.150 +- 0.025 => +-5 sigma window.
#define WIN_SHIFT 13
#define WIN_BASE  (0x3F866000 >> WIN_SHIFT)

// ---- monotone float<->key transform (fallback path only) ----
static __device__ __forceinline__ uint32_t f2key(uint32_t u) {
    return u ^ (uint32_t)(((int32_t)u >> 31) | 0x80000000u);
}
static __device__ __forceinline__ float key2f(uint32_t k) {
    uint32_t m = (uint32_t)((int32_t)k >> 31);
    return __uint_as_float(k ^ (0x80000000u | ~m));
}

// Warp-0 suffix-scan over a 256-bin histogram (descending bins). The lane/slot
// where cumulative count (from the top, plus `base`) crosses kk writes
// {bin, residual-k, bin-count}. Call from warp 0 only; caller syncs around it.
static __device__ __forceinline__ void scan_w0(
    const uint32_t* __restrict__ hist, uint32_t base, uint32_t kk,
    uint32_t* sh_bin, uint32_t* sh_krem, uint32_t* sh_cnt, int lane)
{
    const int b0 = 248 - 8 * lane;                       // lane 0 owns top bins
    uint4 p0 = *reinterpret_cast<const uint4*>(hist + b0);
    uint4 p1 = *reinterpret_cast<const uint4*>(hist + b0 + 4);
    uint32_t h[8] = {p1.w, p1.z, p1.y, p1.x, p0.w, p0.z, p0.y, p0.x}; // descending
    uint32_t sum = 0;
    #pragma unroll
    for (int j = 0; j < 8; j++) sum += h[j];
    uint32_t ex = sum;
    #pragma unroll
    for (int off = 1; off < 32; off <<= 1) {
        uint32_t y = __shfl_up_sync(0xFFFFFFFFu, ex, off);
        if (lane >= off) ex += y;
    }
    uint32_t excl = ex - sum + base;                     // exclusive prefix above my chunk
    #pragma unroll
    for (int j = 0; j < 8; j++) {
        uint32_t c = h[j];
        if (kk > excl && kk <= excl + c) {
            *sh_bin  = (uint32_t)(b0 + 7 - j);
            *sh_krem = kk - excl;
            *sh_cnt  = c;
        }
        excl += c;
    }
}

__global__ void __launch_bounds__(NTHREADS, 4)
kwinners_kernel(const float* __restrict__ s, float* __restrict__ out)
{
    __shared__ uint32_t hist[256];
    __shared__ float    hval[256];          // representative value per bin
    __shared__ uint32_t wabove[NWARPS];
    __shared__ float    fcand[FC_CAP];
    __shared__ uint32_t sh_bin, sh_krem, sh_cnt, sh_fcnt;
    __shared__ float    sh_T;

    const int tid  = threadIdx.x;
    const int lane = tid & 31;
    const int wid  = tid >> 5;
    const unsigned FULL = 0xFFFFFFFFu;

    const size_t row = blockIdx.x;
    const float4* __restrict__ src = reinterpret_cast<const float4*>(s)  + row * (NEURONS / 4);
    float4* __restrict__       dst = reinterpret_cast<float4*>(out)      + row * (NEURONS / 4);

    // ---- single global read: front-batched for max MLP; row stays in registers ----
    float4 v[VPT];
    #pragma unroll
    for (int i = 0; i < VPT; i++) v[i] = __ldcs(&src[tid + i * NTHREADS]);

    hist[tid] = 0u;
    if (tid == 0) { sh_bin = SENT; sh_fcnt = 0u; }
    __syncthreads();                                        // sync #1

    // ---- pass 1: integer-bit classify; sparse in-window histogram ----
    unsigned above = 0;
    #pragma unroll
    for (int i = 0; i < VPT; i++) {
        const float xs[4] = {v[i].x, v[i].y, v[i].z, v[i].w};
        #pragma unroll
        for (int j = 0; j < 4; j++) {
            int b = (__float_as_int(xs[j]) >> WIN_SHIFT) - WIN_BASE;  // <0 below, >=256 above
            above += (b >= 256);
            if ((unsigned)b < 256u) { atomicAdd(&hist[b], 1u); hval[b] = xs[j]; }
        }
    }
    above = __reduce_add_sync(FULL, above);
    if (lane == 0) wabove[wid] = above;
    __syncthreads();                                        // sync #2

    if (wid == 0) {
        uint32_t bse = (lane < NWARPS) ? wabove[lane] : 0u;
        bse = __reduce_add_sync(FULL, bse);
        scan_w0(hist, bse, KSEL, &sh_bin, &sh_krem, &sh_cnt, lane);
    }
    __syncthreads();                                        // sync #3

    float T;
    const uint32_t B = sh_bin;
    if (B != SENT && sh_cnt <= FC_CAP) {
        if (sh_cnt == 1u) {
            T = hval[B];                                    // sole element of crossing bin
        } else {
            const uint32_t krem = sh_krem;
            // collect the few bin-B elements from registers, exact rank-select
            #pragma unroll
            for (int i = 0; i < VPT; i++) {
                const float xs[4] = {v[i].x, v[i].y, v[i].z, v[i].w};
                #pragma unroll
                for (int j = 0; j < 4; j++) {
                    int b = (__float_as_int(xs[j]) >> WIN_SHIFT) - WIN_BASE;
                    if (b == (int)B) fcand[atomicAdd(&sh_fcnt, 1u)] = xs[j];
                }
            }
            __syncthreads();
            const int n = (int)sh_fcnt;                     // == sh_cnt <= FC_CAP
            if (tid < n) {
                float mine = fcand[tid];
                int g = 0, eq = 0;
                for (int j = 0; j < n; j++) {
                    float o = fcand[j];
                    g  += (o > mine);
                    eq += (o == mine);
                }
                if ((uint32_t)g < krem && (uint32_t)(g + eq) >= krem) sh_T = mine;
            }
            __syncthreads();
            T = sh_T;
        }
    } else {
        // ---- exact 4-pass radix-select fallback (window miss / huge tie mass) ----
        uint32_t prefix = 0, kk = KSEL;
        for (int shift = 24; shift >= 0; shift -= 8) {
            __syncthreads();
            hist[tid] = 0u;
            if (tid == 0) sh_bin = SENT;
            __syncthreads();
            #pragma unroll
            for (int i = 0; i < VPT; i++) {
                const float xs[4] = {v[i].x, v[i].y, v[i].z, v[i].w};
                #pragma unroll
                for (int j = 0; j < 4; j++) {
                    uint32_t key = f2key(__float_as_uint(xs[j]));
                    bool valid = (shift == 24) || ((key >> (shift + 8)) == prefix);
                    if (valid) atomicAdd(&hist[(key >> shift) & 0xFFu], 1u);
                }
            }
            __syncthreads();
            if (wid == 0) scan_w0(hist, 0u, kk, &sh_bin, &sh_krem, &sh_cnt, lane);
            __syncthreads();
            prefix = (prefix << 8) | sh_bin;
            kk = sh_krem;
        }
        T = key2f(prefix);
    }

    // ---- apply threshold from registers; streaming stores ----
    #pragma unroll
    for (int i = 0; i < VPT; i++) {
        float4 o;
        o.x = (v[i].x >= T) ? v[i].x : 0.0f;
        o.y = (v[i].y >= T) ? v[i].y : 0.0f;
        o.z = (v[i].z >= T) ? v[i].z : 0.0f;
        o.w = (v[i].w >= T) ? v[i].w : 0.0f;
        __stcs(&dst[tid + i * NTHREADS], o);
    }
}

extern "C" void kernel_launch(void* const* d_in, const int* in_sizes, int n_in,
                              void* d_out, int out_size)
{
    const float* s = (const float*)d_in[0];
    float* out = (float*)d_out;
    const int rows = out_size / NEURONS;   // 16384
    kwinners_kernel<<<rows, NTHREADS>>>(s, out);
}

// round 10
// speedup vs baseline: 1.0693x; 1.0693x over previous
#include <cuda_runtime.h>
#include <cstdint>

#define NEURONS  4096
#define KSEL     512
#define NTHREADS 256
#define VPT      4                 // float4 loads per thread (16 elems/thread)
#define NWARPS   (NTHREADS / 32)
#define FC_CAP   256
#define SENT     0xFFFFFFFFu

// Integer-domain histogram window (bit-monotone for positive floats):
// bins of width 2^13 ulps starting at 0x3F866000 (~1.0498), 256 bins -> hi ~1.2998.
// Threshold for K/N=0.125 on N(0,1) rows is 1.150 +- 0.025 => +-5 sigma window.
#define WIN_SHIFT 13
#define WIN_BASE  (0x3F866000 >> WIN_SHIFT)

// ---- monotone float<->key transform (fallback path only) ----
static __device__ __forceinline__ uint32_t f2key(uint32_t u) {
    return u ^ (uint32_t)(((int32_t)u >> 31) | 0x80000000u);
}
static __device__ __forceinline__ float key2f(uint32_t k) {
    uint32_t m = (uint32_t)((int32_t)k >> 31);
    return __uint_as_float(k ^ (0x80000000u | ~m));
}

// Warp-0 suffix-scan over a 256-bin histogram (descending bins). The lane/slot
// where cumulative count (from the top, plus `base`) crosses kk writes
// {bin, residual-k, bin-count}. Call from warp 0 only; caller syncs around it.
static __device__ __forceinline__ void scan_w0(
    const uint32_t* __restrict__ hist, uint32_t base, uint32_t kk,
    uint32_t* sh_bin, uint32_t* sh_krem, uint32_t* sh_cnt, int lane)
{
    const int b0 = 248 - 8 * lane;                       // lane 0 owns top bins
    uint4 p0 = *reinterpret_cast<const uint4*>(hist + b0);
    uint4 p1 = *reinterpret_cast<const uint4*>(hist + b0 + 4);
    uint32_t h[8] = {p1.w, p1.z, p1.y, p1.x, p0.w, p0.z, p0.y, p0.x}; // descending
    uint32_t sum = 0;
    #pragma unroll
    for (int j = 0; j < 8; j++) sum += h[j];
    uint32_t ex = sum;
    #pragma unroll
    for (int off = 1; off < 32; off <<= 1) {
        uint32_t y = __shfl_up_sync(0xFFFFFFFFu, ex, off);
        if (lane >= off) ex += y;
    }
    uint32_t excl = ex - sum + base;                     // exclusive prefix above my chunk
    #pragma unroll
    for (int j = 0; j < 8; j++) {
        uint32_t c = h[j];
        if (kk > excl && kk <= excl + c) {
            *sh_bin  = (uint32_t)(b0 + 7 - j);
            *sh_krem = kk - excl;
            *sh_cnt  = c;
        }
        excl += c;
    }
}

// Classify one row into a 256-bin in-window histogram; returns per-warp "above" sum
// already stored to wab[wid] (lane 0).
static __device__ __forceinline__ void classify(
    const float4* __restrict__ src, int tid, int lane, int wid,
    uint32_t* __restrict__ hist, float* __restrict__ hval, uint32_t* __restrict__ wab)
{
    unsigned above = 0;
    #pragma unroll
    for (int i = 0; i < VPT; i++) {
        float4 v = src[tid + i * NTHREADS];
        const float xs[4] = {v.x, v.y, v.z, v.w};
        #pragma unroll
        for (int j = 0; j < 4; j++) {
            int b = (__float_as_int(xs[j]) >> WIN_SHIFT) - WIN_BASE; // <0 below, >=256 above
            above += (b >= 256);
            if ((unsigned)b < 256u) { atomicAdd(&hist[b], 1u); hval[b] = xs[j]; }
        }
    }
    above = __reduce_add_sync(0xFFFFFFFFu, above);
    if (lane == 0) wab[wid] = above;
}

// Resolve exact threshold for one row. bin/krem/cnt are the (uniform) scan results.
// May execute __syncthreads (uniformly). hist/sh_* are reused as fallback scratch.
static __device__ __forceinline__ float resolve(
    const float4* __restrict__ src, int tid, int lane, int wid,
    uint32_t B, uint32_t krem, uint32_t cnt,
    const float* __restrict__ hval, float* __restrict__ fcand,
    uint32_t* sh_fcnt, float* sh_T,
    uint32_t* __restrict__ hist, uint32_t* sh_bin, uint32_t* sh_krem, uint32_t* sh_cnt)
{
    if (B != SENT && cnt <= FC_CAP) {
        if (cnt == 1u) return hval[B];          // sole element of crossing bin (no syncs)
        // collect bin-B elements (row re-read hits L1), exact rank-select
        #pragma unroll
        for (int i = 0; i < VPT; i++) {
            float4 v = src[tid + i * NTHREADS];
            const float xs[4] = {v.x, v.y, v.z, v.w};
            #pragma unroll
            for (int j = 0; j < 4; j++) {
                int b = (__float_as_int(xs[j]) >> WIN_SHIFT) - WIN_BASE;
                if (b == (int)B) fcand[atomicAdd(sh_fcnt, 1u)] = xs[j];
            }
        }
        __syncthreads();
        const int n = (int)*sh_fcnt;            // == cnt <= FC_CAP
        if (tid < n) {
            float mine = fcand[tid];
            int g = 0, eq = 0;
            for (int j = 0; j < n; j++) {
                float o = fcand[j];
                g  += (o > mine);
                eq += (o == mine);
            }
            if ((uint32_t)g < krem && (uint32_t)(g + eq) >= krem) *sh_T = mine;
        }
        __syncthreads();
        return *sh_T;
    }
    // ---- exact 4-pass radix-select fallback (window miss / huge tie mass) ----
    uint32_t prefix = 0, kk = KSEL;
    for (int shift = 24; shift >= 0; shift -= 8) {
        __syncthreads();
        hist[tid] = 0u;
        if (tid == 0) *sh_bin = SENT;
        __syncthreads();
        #pragma unroll
        for (int i = 0; i < VPT; i++) {
            float4 v = src[tid + i * NTHREADS];
            const float xs[4] = {v.x, v.y, v.z, v.w};
            #pragma unroll
            for (int j = 0; j < 4; j++) {
                uint32_t key = f2key(__float_as_uint(xs[j]));
                bool valid = (shift == 24) || ((key >> (shift + 8)) == prefix);
                if (valid) atomicAdd(&hist[(key >> shift) & 0xFFu], 1u);
            }
        }
        __syncthreads();
        if (wid == 0) scan_w0(hist, 0u, kk, sh_bin, sh_krem, sh_cnt, lane);
        __syncthreads();
        prefix = (prefix << 8) | *sh_bin;
        kk = *sh_krem;
    }
    return key2f(prefix);
}

static __device__ __forceinline__ void apply(
    const float4* __restrict__ src, float4* __restrict__ dst, int tid, float T)
{
    #pragma unroll
    for (int i = 0; i < VPT; i++) {
        float4 v = __ldcs(&src[tid + i * NTHREADS]);   // last use: evict-first
        float4 o;
        o.x = (v.x >= T) ? v.x : 0.0f;
        o.y = (v.y >= T) ? v.y : 0.0f;
        o.z = (v.z >= T) ? v.z : 0.0f;
        o.w = (v.w >= T) ? v.w : 0.0f;
        __stcs(&dst[tid + i * NTHREADS], o);
    }
}

__global__ void __launch_bounds__(NTHREADS, 6)
kwinners_kernel(const float* __restrict__ s, float* __restrict__ out, int rows)
{
    __shared__ uint32_t histA[256], histB[256];
    __shared__ float    hvalA[256], hvalB[256];
    __shared__ uint32_t wabA[NWARPS], wabB[NWARPS];
    __shared__ float    fcandA[FC_CAP], fcandB[FC_CAP];
    __shared__ uint32_t binA, kremA, cntA, fcntA, binB, kremB, cntB, fcntB;
    __shared__ float    shTA, shTB;

    const int tid  = threadIdx.x;
    const int lane = tid & 31;
    const int wid  = tid >> 5;
    const unsigned FULL = 0xFFFFFFFFu;

    const size_t rA = (size_t)blockIdx.x * 2;
    const bool hasB = (rA + 1) < (size_t)rows;
    const float4* __restrict__ srcA = reinterpret_cast<const float4*>(s)   + rA * (NEURONS / 4);
    float4* __restrict__       dstA = reinterpret_cast<float4*>(out)       + rA * (NEURONS / 4);
    const float4* __restrict__ srcB = srcA + (NEURONS / 4);
    float4* __restrict__       dstB = dstA + (NEURONS / 4);

    histA[tid] = 0u; histB[tid] = 0u;
    if (tid == 0) { binA = SENT; binB = SENT; fcntA = 0u; fcntB = 0u; }
    __syncthreads();                                        // S1

    // ---- classify row A (DRAM stream A) ----
    classify(srcA, tid, lane, wid, histA, hvalA, wabA);
    __syncthreads();                                        // S2

    // ---- warp0 scans A while all warps classify row B (DRAM stream B) ----
    if (wid == 0) {
        uint32_t bse = (lane < NWARPS) ? wabA[lane] : 0u;
        bse = __reduce_add_sync(FULL, bse);
        scan_w0(histA, bse, KSEL, &binA, &kremA, &cntA, lane);
    }
    if (hasB) classify(srcB, tid, lane, wid, histB, hvalB, wabB);
    __syncthreads();                                        // S3

    // ---- warp0 scans B while all warps resolve + apply row A (store stream A) ----
    if (hasB && wid == 0) {
        uint32_t bse = (lane < NWARPS) ? wabB[lane] : 0u;
        bse = __reduce_add_sync(FULL, bse);
        scan_w0(histB, bse, KSEL, &binB, &kremB, &cntB, lane);
    }
    {
        float TA = resolve(srcA, tid, lane, wid, binA, kremA, cntA,
                           hvalA, fcandA, &fcntA, &shTA,
                           histA, &binA, &kremA, &cntA);
        apply(srcA, dstA, tid, TA);
    }
    __syncthreads();                                        // S4 (scanB visible)

    // ---- resolve + apply row B (store stream B) ----
    if (hasB) {
        float TB = resolve(srcB, tid, lane, wid, binB, kremB, cntB,
                           hvalB, fcandB, &fcntB, &shTB,
                           histB, &binB, &kremB, &cntB);
        apply(srcB, dstB, tid, TB);
    }
}

extern "C" void kernel_launch(void* const* d_in, const int* in_sizes, int n_in,
                              void* d_out, int out_size)
{
    const float* s = (const float*)d_in[0];
    float* out = (float*)d_out;
    const int rows = out_size / NEURONS;   // 16384
    kwinners_kernel<<<(rows + 1) / 2, NTHREADS>>>(s, out, rows);
}

// round 11
// speedup vs baseline: 1.0948x; 1.0238x over previous
#include <cuda_runtime.h>
#include <cstdint>

#define NEURONS  4096
#define KSEL     512
#define NTHREADS 256
#define VPT      4                 // float4 loads per thread (16 elems/thread)
#define NWARPS   (NTHREADS / 32)
#define FC_CAP   256
#define SENT     0xFFFFFFFFu

// Integer-domain histogram window (bit-monotone for positive floats):
// bins of width 2^13 ulps starting at 0x3F866000 (~1.0498), 256 bins -> hi ~1.2998.
// Threshold for K/N=0.125 on N(0,1) rows is 1.150 +- 0.025 => +-5 sigma window.
#define WIN_SHIFT 13
#define WIN_BASE  (0x3F866000 >> WIN_SHIFT)

// ---- monotone float<->key transform (fallback path only) ----
static __device__ __forceinline__ uint32_t f2key(uint32_t u) {
    return u ^ (uint32_t)(((int32_t)u >> 31) | 0x80000000u);
}
static __device__ __forceinline__ float key2f(uint32_t k) {
    uint32_t m = (uint32_t)((int32_t)k >> 31);
    return __uint_as_float(k ^ (0x80000000u | ~m));
}

// Warp-0 suffix-scan over a 256-bin histogram (descending bins). The lane/slot
// where cumulative count (from the top, plus `base`) crosses kk writes
// {bin, residual-k, bin-count}. Call from warp 0 only; caller syncs around it.
static __device__ __forceinline__ void scan_w0(
    const uint32_t* __restrict__ hist, uint32_t base, uint32_t kk,
    uint32_t* sh_bin, uint32_t* sh_krem, uint32_t* sh_cnt, int lane)
{
    const int b0 = 248 - 8 * lane;                       // lane 0 owns top bins
    uint4 p0 = *reinterpret_cast<const uint4*>(hist + b0);
    uint4 p1 = *reinterpret_cast<const uint4*>(hist + b0 + 4);
    uint32_t h[8] = {p1.w, p1.z, p1.y, p1.x, p0.w, p0.z, p0.y, p0.x}; // descending
    uint32_t sum = 0;
    #pragma unroll
    for (int j = 0; j < 8; j++) sum += h[j];
    uint32_t ex = sum;
    #pragma unroll
    for (int off = 1; off < 32; off <<= 1) {
        uint32_t y = __shfl_up_sync(0xFFFFFFFFu, ex, off);
        if (lane >= off) ex += y;
    }
    uint32_t excl = ex - sum + base;                     // exclusive prefix above my chunk
    #pragma unroll
    for (int j = 0; j < 8; j++) {
        uint32_t c = h[j];
        if (kk > excl && kk <= excl + c) {
            *sh_bin  = (uint32_t)(b0 + 7 - j);
            *sh_krem = kk - excl;
            *sh_cnt  = c;
        }
        excl += c;
    }
}

__global__ void __launch_bounds__(NTHREADS, 6)
kwinners_kernel(const float* __restrict__ s, float* __restrict__ out)
{
    __shared__ float4   rowc[NEURONS / 4];  // full row cache (16 KB)
    __shared__ uint32_t hist[256];
    __shared__ float    hval[256];          // representative value per bin
    __shared__ uint32_t wabove[NWARPS];
    __shared__ float    fcand[FC_CAP];
    __shared__ uint32_t sh_bin, sh_krem, sh_cnt, sh_fcnt;
    __shared__ float    sh_T;

    const int tid  = threadIdx.x;
    const int lane = tid & 31;
    const int wid  = tid >> 5;
    const unsigned FULL = 0xFFFFFFFFu;

    const size_t row = blockIdx.x;
    const float4* __restrict__ src = reinterpret_cast<const float4*>(s)  + row * (NEURONS / 4);
    float4* __restrict__       dst = reinterpret_cast<float4*>(out)      + row * (NEURONS / 4);

    hist[tid] = 0u;
    if (tid == 0) { sh_bin = SENT; sh_fcnt = 0u; }
    __syncthreads();                                        // sync #1

    // ---- pass 1: single DRAM read (evict-first), cache to smem, classify.
    //      Memoize first two in-window values per thread (mean ~1, P(>2)~8%).
    unsigned above = 0, mcnt = 0;
    float m0 = 0.0f, m1 = 0.0f;
    #pragma unroll
    for (int i = 0; i < VPT; i++) {
        float4 v = __ldcs(&src[tid + i * NTHREADS]);
        rowc[tid + i * NTHREADS] = v;
        const float xs[4] = {v.x, v.y, v.z, v.w};
        #pragma unroll
        for (int j = 0; j < 4; j++) {
            int b = (__float_as_int(xs[j]) >> WIN_SHIFT) - WIN_BASE;  // <0 below, >=256 above
            above += (b >= 256);
            if ((unsigned)b < 256u) {
                atomicAdd(&hist[b], 1u);
                hval[b] = xs[j];
                if (mcnt == 0u) m0 = xs[j]; else if (mcnt == 1u) m1 = xs[j];
                mcnt++;
            }
        }
    }
    above = __reduce_add_sync(FULL, above);
    if (lane == 0) wabove[wid] = above;
    __syncthreads();                                        // sync #2

    if (wid == 0) {
        uint32_t bse = (lane < NWARPS) ? wabove[lane] : 0u;
        bse = __reduce_add_sync(FULL, bse);
        scan_w0(hist, bse, KSEL, &sh_bin, &sh_krem, &sh_cnt, lane);
    }
    __syncthreads();                                        // sync #3

    float T;
    const uint32_t B = sh_bin;
    if (B != SENT && sh_cnt <= FC_CAP) {
        if (sh_cnt == 1u) {
            T = hval[B];                                    // sole element of crossing bin
        } else {
            const uint32_t krem = sh_krem;
            // collect bin-B elements from memo registers (smem rescan only on overflow)
            if (mcnt <= 2u) {
                if (mcnt >= 1u && ((__float_as_int(m0) >> WIN_SHIFT) - WIN_BASE) == (int)B)
                    fcand[atomicAdd(&sh_fcnt, 1u)] = m0;
                if (mcnt == 2u && ((__float_as_int(m1) >> WIN_SHIFT) - WIN_BASE) == (int)B)
                    fcand[atomicAdd(&sh_fcnt, 1u)] = m1;
            } else {
                #pragma unroll
                for (int i = 0; i < VPT; i++) {
                    float4 v = rowc[tid + i * NTHREADS];
                    const float xs[4] = {v.x, v.y, v.z, v.w};
                    #pragma unroll
                    for (int j = 0; j < 4; j++) {
                        int b = (__float_as_int(xs[j]) >> WIN_SHIFT) - WIN_BASE;
                        if (b == (int)B) fcand[atomicAdd(&sh_fcnt, 1u)] = xs[j];
                    }
                }
            }
            __syncthreads();
            const int n = (int)sh_fcnt;                     // == sh_cnt <= FC_CAP
            if (tid < n) {
                float mine = fcand[tid];
                int g = 0, eq = 0;
                for (int j = 0; j < n; j++) {
                    float o = fcand[j];
                    g  += (o > mine);
                    eq += (o == mine);
                }
                if ((uint32_t)g < krem && (uint32_t)(g + eq) >= krem) sh_T = mine;
            }
            __syncthreads();
            T = sh_T;
        }
    } else {
        // ---- exact 4-pass radix-select fallback (window miss / huge tie mass);
        //      reads the smem row cache, zero extra global traffic ----
        uint32_t prefix = 0, kk = KSEL;
        for (int shift = 24; shift >= 0; shift -= 8) {
            __syncthreads();
            hist[tid] = 0u;
            if (tid == 0) sh_bin = SENT;
            __syncthreads();
            #pragma unroll
            for (int i = 0; i < VPT; i++) {
                float4 v = rowc[tid + i * NTHREADS];
                const float xs[4] = {v.x, v.y, v.z, v.w};
                #pragma unroll
                for (int j = 0; j < 4; j++) {
                    uint32_t key = f2key(__float_as_uint(xs[j]));
                    bool valid = (shift == 24) || ((key >> (shift + 8)) == prefix);
                    if (valid) atomicAdd(&hist[(key >> shift) & 0xFFu], 1u);
                }
            }
            __syncthreads();
            if (wid == 0) scan_w0(hist, 0u, kk, &sh_bin, &sh_krem, &sh_cnt, lane);
            __syncthreads();
            prefix = (prefix << 8) | sh_bin;
            kk = sh_krem;
        }
        T = key2f(prefix);
    }

    // ---- apply threshold from the smem row cache; streaming stores ----
    #pragma unroll
    for (int i = 0; i < VPT; i++) {
        float4 v = rowc[tid + i * NTHREADS];
        float4 o;
        o.x = (v.x >= T) ? v.x : 0.0f;
        o.y = (v.y >= T) ? v.y : 0.0f;
        o.z = (v.z >= T) ? v.z : 0.0f;
        o.w = (v.w >= T) ? v.w : 0.0f;
        __stcs(&dst[tid + i * NTHREADS], o);
    }
}

extern "C" void kernel_launch(void* const* d_in, const int* in_sizes, int n_in,
                              void* d_out, int out_size)
{
    const float* s = (const float*)d_in[0];
    float* out = (float*)d_out;
    const int rows = out_size / NEURONS;   // 16384
    kwinners_kernel<<<rows, NTHREADS>>>(s, out);
}